// round 6
// baseline (speedup 1.0000x reference)
#include <cuda_runtime.h>
#include <math.h>

#define BB 64
#define LL 64
#define GRID 128
#define TPB 256
#define NSLOT 128

__device__ float g_H[BB*NSLOT*512];      // h per (batch, slot)
__device__ float g_C[BB*NSLOT*512];      // c per (batch, slot)
// vV cache: block-private region per block: [b][slot][40] rows (side*20+g*4+hgoff)
__device__ float g_V[(size_t)GRID*BB*NSLOT*40];
__device__ float g_cwp[2][128*128];      // loop cw partials, double-buffered by parity
__device__ float g_cwp0[4032*128];       // iter-0 cw partials
__device__ float g_cw0[4032];            // iter-0 folded cw
__device__ unsigned g_barrier;

__device__ __forceinline__ float sigm(float x){ return 1.0f/(1.0f+expf(-x)); }

__device__ __forceinline__ void ffma2(float2 &acc, float2 a, float2 b){
    asm("fma.rn.f32x2 %0, %1, %2, %0;"
        : "+l"(reinterpret_cast<unsigned long long&>(acc))
        : "l"(reinterpret_cast<unsigned long long&>(a)),
          "l"(reinterpret_cast<unsigned long long&>(b)));
}

__device__ __forceinline__ void grid_barrier(unsigned target){
    __syncthreads();
    if (threadIdx.x == 0){
        asm volatile("red.release.gpu.global.add.u32 [%0], 1;"
                     :: "l"(&g_barrier) : "memory");
        unsigned v;
        do {
            asm volatile("ld.acquire.gpu.global.u32 %0, [%1];"
                         : "=r"(v) : "l"(&g_barrier) : "memory");
        } while (v < target);
    }
    __syncthreads();
}

// ---------------------------------------------------------------------------
// Word GEMM: leaf h,c
// ---------------------------------------------------------------------------
__global__ __launch_bounds__(256) void word_gemm(
    const float* __restrict__ x, const float* __restrict__ w,
    const float* __restrict__ bias)
{
    __shared__ float As[64][33];
    __shared__ float Ws[64][33];
    int tid = threadIdx.x;
    int tx = tid & 15, ty = tid >> 4;
    int m0 = blockIdx.y * 64;
    int c0 = blockIdx.x * 64;
    float acc[4][4] = {};

    for (int k0 = 0; k0 < 512; k0 += 32) {
        #pragma unroll
        for (int t = tid; t < 64 * 32; t += 256) {
            int r = t >> 5, kk = t & 31;
            As[r][kk] = x[(m0 + r) * 512 + k0 + kk];
            Ws[r][kk] = w[(c0 + r) * 512 + k0 + kk];
        }
        __syncthreads();
        #pragma unroll
        for (int kk = 0; kk < 32; kk++) {
            float a[4], b[4];
            #pragma unroll
            for (int r = 0; r < 4; r++) a[r] = As[ty * 4 + r][kk];
            #pragma unroll
            for (int cc = 0; cc < 4; cc++) b[cc] = Ws[tx * 4 + cc][kk];
            #pragma unroll
            for (int r = 0; r < 4; r++)
                #pragma unroll
                for (int cc = 0; cc < 4; cc++)
                    acc[r][cc] += a[r] * b[cc];
        }
        __syncthreads();
    }
    #pragma unroll
    for (int r = 0; r < 4; r++) {
        int m = m0 + ty * 4 + r;
        int b = m >> 6, leaf = m & 63;
        int base = (b * NSLOT + leaf) * 512;
        #pragma unroll
        for (int cc = 0; cc < 4; cc++) {
            int col = c0 + tx * 4 + cc;
            float v = acc[r][cc] + bias[col];
            if (col < 512) g_H[base + col] = v;
            else           g_C[base + col - 512] = v;
        }
    }
}

__global__ void init_state(){
    if (blockIdx.x == 0 && threadIdx.x == 0) g_barrier = 0u;
}

// ---------------------------------------------------------------------------
// Persistent kernel: vV prologue + iter0 epilogue + 63-iteration loop
// ---------------------------------------------------------------------------
#define W_STRIDE 516
#define A_STRIDE 132
#define WRES_F   (40*W_STRIDE)          // 20640
#define ASB_F    (64*A_STRIDE)          // 8448
#define SVN_F    (64*40)                // 2560
#define SMEM_BYTES ((WRES_F + 2*ASB_F + SVN_F)*4)

__global__ __launch_bounds__(TPB, 1) void tree_loop(
    const int* __restrict__ length, const float* __restrict__ q,
    const float* __restrict__ wcomp, const float* __restrict__ bcomp,
    float* __restrict__ out)
{
    extern __shared__ float smem[];
    float* Wblk  = smem;
    float* Asb0  = smem + WRES_F;
    float* Asb1  = smem + WRES_F + ASB_F;
    float* sVnew = smem + WRES_F + 2*ASB_F;

    __shared__ unsigned char s_vh[BB][64];
    __shared__ unsigned char s_pk[BB][64];
    __shared__ float s_cw[BB][64];
    __shared__ int2  s_fresh[BB];
    __shared__ int   s_node[BB];        // slot to run vV-GEMM on (-1 = none)
    __shared__ int   s_len[BB];
    __shared__ int   s_rl[128], s_rr[128], s_rst[128], s_rb[128], s_rid[128];
    __shared__ unsigned char s_rln[128], s_rrn[128];
    __shared__ int   s_rcnt[BB], s_roff[BB];
    __shared__ int   s_nrows;

    const int tid = threadIdx.x, blk = blockIdx.x;
    const int tx = tid & 3, ty = tid >> 2;          // epilogue roles
    const int tx2 = tid & 7, ty2 = tid >> 3;        // GEMM roles
    const int lane = tid & 31, warp = tid >> 5;
    const int hg = blk * 4 + tx;
    float* gVblk = g_V + (size_t)blk * (BB * NSLOT * 40);

    // resident W: Wblk[r2][k], r2 = side*20 + g*4 + hgoff, k in [0,512)
    for (int idx = tid; idx < 40 * 512; idx += TPB) {
        int r2 = idx >> 9, k = idx & 511;
        int side = r2 / 20, rem = r2 % 20, g = rem >> 2, hgo = rem & 3;
        Wblk[r2 * W_STRIDE + k] = wcomp[(g * 512 + blk * 4 + hgo) * 1024 + side * 512 + k];
    }
    const float qv  = q[hg];
    const float bi  = bcomp[hg],        bfl = bcomp[512 + hg], bfr = bcomp[1024 + hg];
    const float bu  = bcomp[1536 + hg], bo  = bcomp[2048 + hg];
    if (tid < BB) s_len[tid] = length[tid];
    __syncthreads();

    // ---------------- GEMM lambda: vV for <=64 nodes (s_node) --------------
    auto gemm_pass = [&](){
        float2 acc[5][2];
        #pragma unroll
        for (int rr = 0; rr < 5; rr++)
            #pragma unroll
            for (int nn = 0; nn < 2; nn++) acc[rr][nn] = make_float2(0.f, 0.f);

        float4 pf[8];
        #pragma unroll
        for (int ii = 0; ii < 8; ii++) {
            int f = tid + 256 * ii; int row = f >> 5, c4 = f & 31;
            int slot = s_node[row];
            pf[ii] = (slot >= 0)
                   ? __ldcg((const float4*)&g_H[(row * NSLOT + slot) * 512 + c4 * 4])
                   : make_float4(0.f, 0.f, 0.f, 0.f);
        }
        #pragma unroll
        for (int ii = 0; ii < 8; ii++) {
            int f = tid + 256 * ii; int row = f >> 5, c4 = f & 31;
            ((float4*)(Asb0 + row * A_STRIDE))[c4] = pf[ii];
        }
        __syncthreads();
        #pragma unroll
        for (int c = 0; c < 4; c++) {
            if (c < 3) {
                #pragma unroll
                for (int ii = 0; ii < 8; ii++) {
                    int f = tid + 256 * ii; int row = f >> 5, c4 = f & 31;
                    int slot = s_node[row];
                    pf[ii] = (slot >= 0)
                           ? __ldcg((const float4*)&g_H[(row * NSLOT + slot) * 512 + (c + 1) * 128 + c4 * 4])
                           : make_float4(0.f, 0.f, 0.f, 0.f);
                }
            }
            const float* A = (c & 1) ? Asb1 : Asb0;
            #pragma unroll 8
            for (int k4 = 0; k4 < 32; k4++) {
                float4 wv[5], av[2];
                #pragma unroll
                for (int rr = 0; rr < 5; rr++)
                    wv[rr] = ((const float4*)(Wblk + (rr * 8 + tx2) * W_STRIDE))[c * 32 + k4];
                #pragma unroll
                for (int nn = 0; nn < 2; nn++)
                    av[nn] = ((const float4*)(A + (ty2 * 2 + nn) * A_STRIDE))[k4];
                #pragma unroll
                for (int rr = 0; rr < 5; rr++)
                    #pragma unroll
                    for (int nn = 0; nn < 2; nn++) {
                        ffma2(acc[rr][nn], make_float2(wv[rr].x, wv[rr].y),
                                           make_float2(av[nn].x, av[nn].y));
                        ffma2(acc[rr][nn], make_float2(wv[rr].z, wv[rr].w),
                                           make_float2(av[nn].z, av[nn].w));
                    }
            }
            if (c < 3) {
                float* An = (c & 1) ? Asb0 : Asb1;
                #pragma unroll
                for (int ii = 0; ii < 8; ii++) {
                    int f = tid + 256 * ii; int row = f >> 5, c4 = f & 31;
                    ((float4*)(An + row * A_STRIDE))[c4] = pf[ii];
                }
            }
            __syncthreads();
        }
        #pragma unroll
        for (int nn = 0; nn < 2; nn++) {
            int b = ty2 * 2 + nn;
            int slot = s_node[b];
            if (slot >= 0) {
                #pragma unroll
                for (int rr = 0; rr < 5; rr++) {
                    int r2 = rr * 8 + tx2;
                    float v = acc[rr][nn].x + acc[rr][nn].y;
                    gVblk[(b * NSLOT + slot) * 40 + r2] = v;
                    sVnew[b * 40 + r2] = v;
                }
            }
        }
    };

    // ---------------- epilogue lambda: gates for nrows fresh pairs ----------
    auto epilogue = [&](int nrows, float* cwdst){
        #pragma unroll
        for (int r = 0; r < 2; r++) {
            int row = ty * 2 + r;
            float p = 0.f;
            if (row < nrows) {
                int b = s_rb[row];
                int lsl = s_rl[row], rsl = s_rr[row];
                const float* VL = s_rln[row] ? (sVnew + b * 40)
                                             : (gVblk + (b * NSLOT + lsl) * 40);
                const float* VR = s_rrn[row] ? (sVnew + b * 40)
                                             : (gVblk + (b * NSLOT + rsl) * 40);
                float vg[5];
                #pragma unroll
                for (int g = 0; g < 5; g++)
                    vg[g] = VL[g * 4 + tx] + VR[20 + g * 4 + tx];
                float cl = g_C[(b * NSLOT + lsl) * 512 + hg];
                float cr = g_C[(b * NSLOT + rsl) * 512 + hg];
                float cn = cl * sigm(vg[1] + bfl + 1.f) + cr * sigm(vg[2] + bfr + 1.f)
                         + tanhf(vg[3] + bu) * sigm(vg[0] + bi);
                float hn = sigm(vg[4] + bo) * tanhf(cn);
                int st = (b * NSLOT + s_rst[row]) * 512;
                g_H[st + hg] = hn;
                g_C[st + hg] = cn;
                p = hn * qv;
            }
            p += __shfl_xor_sync(0xffffffffu, p, 1);
            p += __shfl_xor_sync(0xffffffffu, p, 2);
            if (row < nrows && tx == 0) cwdst[s_rid[row] * 128 + blk] = p;
        }
    };

    unsigned target = 0;

    // ======== P1: vV for all 64 leaf slots (64 passes, block-private) =======
    for (int pass = 0; pass < 64; pass++) {
        if (tid < BB) s_node[tid] = pass;
        __syncthreads();
        gemm_pass();
        __syncthreads();
    }

    // ======== P2: iteration-0 epilogue: all 63 pairs per batch ==============
    for (int pass = 0; pass < 32; pass++) {
        if (tid < 128) {
            int R = pass * 128 + tid;
            if (R < 4032) {
                int b = R / 63, j = R - b * 63;
                s_rb[tid] = b; s_rl[tid] = j; s_rr[tid] = j + 1;
                s_rst[tid] = 64 + j; s_rid[tid] = R;
                s_rln[tid] = 0; s_rrn[tid] = 0;
            }
        }
        __syncthreads();
        int nr = 4032 - pass * 128; if (nr > 128) nr = 128;
        epilogue(nr, g_cwp0);
        __syncthreads();
    }
    target += GRID; grid_barrier(target);

    // ======== P3: fold iter-0 cw partials (each block owns 32 rids) =========
    {
        #pragma unroll
        for (int t = 0; t < 4; t++) {
            int rid = blk * 32 + warp * 4 + t;
            if (rid < 4032) {
                float4 v = __ldcg((const float4*)&g_cwp0[rid * 128 + lane * 4]);
                float s = (v.x + v.y) + (v.z + v.w);
                #pragma unroll
                for (int o = 16; o > 0; o >>= 1) s += __shfl_xor_sync(0xffffffffu, s, o);
                if (lane == 0) g_cw0[rid] = s;
            }
        }
    }
    target += GRID; grid_barrier(target);

    // ======== loop state init ================================================
    for (int t = tid; t < BB * 64; t += TPB) {
        int b = t >> 6, j = t & 63;
        s_vh[b][j] = (unsigned char)j;
        s_pk[b][j] = (unsigned char)(64 + j);
        s_cw[b][j] = (j < 63) ? __ldcg(&g_cw0[b * 63 + j]) : -1e9f;
    }
    if (tid < BB) s_fresh[tid] = make_int2(-1, -1);
    __syncthreads();

    // ======== main loop: i = 0..62, one grid barrier each ===================
    for (int i = 0; i < 63; i++) {
        const int n = 63 - i;

        // (a) fold cw partials from previous iteration
        if (i > 0) {
            const float* cwsrc = g_cwp[i & 1];
            #pragma unroll
            for (int rr = 0; rr < 16; rr++) {
                int rid = warp + 8 * rr;
                int b = rid >> 1;
                int2 fr = s_fresh[b];
                int pidx = (rid & 1) ? fr.y : fr.x;
                if (pidx >= 0) {
                    float4 v = __ldcg((const float4*)&cwsrc[rid * 128 + lane * 4]);
                    float s = (v.x + v.y) + (v.z + v.w);
                    #pragma unroll
                    for (int o = 16; o > 0; o >>= 1) s += __shfl_xor_sync(0xffffffffu, s, o);
                    if (lane == 0) s_cw[b][pidx] = s;
                }
            }
        }
        __syncthreads();

        // (b) select (redundant per block, deterministic)
        if (tid < BB) {
            int b = tid, len = s_len[b];
            int s;
            if (i + 1 >= len) s = -2;
            else if (n == 1) s = 0;
            else {
                float best = -2e9f; int bj = 0;
                for (int j = 0; j < n; j++) {
                    float v = (i + 1 + j < len) ? s_cw[b][j] : -1e9f;
                    if (v > best) { best = v; bj = j; }
                }
                s = bj;
            }
            int merged = -1;
            int2 fr = make_int2(-1, -1);
            if (s >= 0) {
                merged = s_pk[b][s];
                s_vh[b][s] = (unsigned char)merged;
                for (int j = s + 1; j < n; j++) s_vh[b][j] = s_vh[b][j + 1];
                for (int j = s; j < n - 1; j++) { s_pk[b][j] = s_pk[b][j + 1]; s_cw[b][j] = s_cw[b][j + 1]; }
                if (i < 62) {
                    if (s >= 1)     fr.x = s - 1;
                    if (s <= n - 2) fr.y = s;
                }
            }
            s_fresh[b] = fr;
            s_node[b] = (i < 62) ? merged : -1;
            s_rcnt[b] = (fr.x >= 0) + (fr.y >= 0);
        }
        __syncthreads();
        if (tid == 0) {
            int acc = 0;
            for (int b = 0; b < BB; b++) { s_roff[b] = acc; acc += s_rcnt[b]; }
            s_nrows = acc;
        }
        __syncthreads();
        if (tid < BB) {
            int b = tid; int2 fr = s_fresh[b]; int o = s_roff[b];
            if (fr.x >= 0) {               // pair s-1: (old, NEW)
                int p = fr.x;
                s_rb[o] = b; s_rl[o] = s_vh[b][p]; s_rr[o] = s_vh[b][p + 1];
                s_rln[o] = 0; s_rrn[o] = 1;
                s_rst[o] = s_pk[b][p]; s_rid[o] = b * 2 + 0; o++;
            }
            if (fr.y >= 0) {               // pair s: (NEW, old)
                int p = fr.y;
                s_rb[o] = b; s_rl[o] = s_vh[b][p]; s_rr[o] = s_vh[b][p + 1];
                s_rln[o] = 1; s_rrn[o] = 0;
                s_rst[o] = s_pk[b][p]; s_rid[o] = b * 2 + 1; o++;
            }
        }
        __syncthreads();

        // (c) vV GEMM for the merged node of each batch, (d) epilogue
        if (i < 62) {
            gemm_pass();
            __syncthreads();
            epilogue(s_nrows, g_cwp[(i + 1) & 1]);
        }
        target += GRID; grid_barrier(target);
    }

    // ======== output =========================================================
    if (blk < BB) {
        int base = (blk * NSLOT + s_vh[blk][0]) * 512;
        out[blk * 512 + tid]                  = __ldcg(&g_H[base + tid]);
        out[blk * 512 + 256 + tid]            = __ldcg(&g_H[base + 256 + tid]);
        out[BB * 512 + blk * 512 + tid]       = __ldcg(&g_C[base + tid]);
        out[BB * 512 + blk * 512 + 256 + tid] = __ldcg(&g_C[base + 256 + tid]);
    }
}

// ---------------------------------------------------------------------------
extern "C" void kernel_launch(void* const* d_in, const int* in_sizes, int n_in,
                              void* d_out, int out_size)
{
    const float* x      = (const float*)d_in[0];
    const int*   length = (const int*)  d_in[1];
    const float* w_word = (const float*)d_in[2];
    const float* b_word = (const float*)d_in[3];
    const float* w_comp = (const float*)d_in[4];
    const float* b_comp = (const float*)d_in[5];
    const float* q      = (const float*)d_in[6];
    float* out = (float*)d_out;

    static int smem_set = 0;
    if (!smem_set) {
        cudaFuncSetAttribute(tree_loop, cudaFuncAttributeMaxDynamicSharedMemorySize,
                             SMEM_BYTES);
        smem_set = 1;
    }

    word_gemm<<<dim3(16, 64), 256>>>(x, w_word, b_word);
    init_state<<<1, 32>>>();
    tree_loop<<<GRID, TPB, SMEM_BYTES>>>(length, q, w_comp, b_comp, out);
}

// round 7
// speedup vs baseline: 1.2997x; 1.2997x over previous
#include <cuda_runtime.h>
#include <math.h>

#define BB 64
#define LL 64
#define GRID 128
#define TPB 256
#define NSLOT 128
#define NST (BB*NSLOT*512)

__device__ float g_H[NST];
__device__ float g_C[NST];
__device__ float g_cwp[2][128*128];   // cw partials, parity double-buffered
__device__ float g_cw0[BB*63];
__device__ unsigned g_barrier;

__device__ __forceinline__ float sigm(float x){ return 1.0f/(1.0f+expf(-x)); }

__device__ __forceinline__ void ffma2(float2 &acc, float2 a, float2 b){
    asm("fma.rn.f32x2 %0, %1, %2, %0;"
        : "+l"(reinterpret_cast<unsigned long long&>(acc))
        : "l"(reinterpret_cast<unsigned long long&>(a)),
          "l"(reinterpret_cast<unsigned long long&>(b)));
}

__device__ __forceinline__ void grid_barrier(unsigned target){
    __syncthreads();
    if (threadIdx.x == 0){
        asm volatile("red.release.gpu.global.add.u32 [%0], 1;"
                     :: "l"(&g_barrier) : "memory");
        unsigned v;
        do {
            asm volatile("ld.acquire.gpu.global.u32 %0, [%1];"
                         : "=r"(v) : "l"(&g_barrier) : "memory");
        } while (v < target);
    }
    __syncthreads();
}

// ---------------------------------------------------------------------------
__global__ __launch_bounds__(256) void word_gemm(
    const float* __restrict__ x, const float* __restrict__ w,
    const float* __restrict__ bias)
{
    __shared__ float As[64][33];
    __shared__ float Ws[64][33];
    int tid = threadIdx.x;
    int tx = tid & 15, ty = tid >> 4;
    int m0 = blockIdx.y * 64;
    int c0 = blockIdx.x * 64;
    float acc[4][4] = {};

    for (int k0 = 0; k0 < 512; k0 += 32) {
        #pragma unroll
        for (int t = tid; t < 64 * 32; t += 256) {
            int r = t >> 5, kk = t & 31;
            As[r][kk] = x[(m0 + r) * 512 + k0 + kk];
            Ws[r][kk] = w[(c0 + r) * 512 + k0 + kk];
        }
        __syncthreads();
        #pragma unroll
        for (int kk = 0; kk < 32; kk++) {
            float a[4], b[4];
            #pragma unroll
            for (int r = 0; r < 4; r++) a[r] = As[ty * 4 + r][kk];
            #pragma unroll
            for (int cc = 0; cc < 4; cc++) b[cc] = Ws[tx * 4 + cc][kk];
            #pragma unroll
            for (int r = 0; r < 4; r++)
                #pragma unroll
                for (int cc = 0; cc < 4; cc++)
                    acc[r][cc] += a[r] * b[cc];
        }
        __syncthreads();
    }
    #pragma unroll
    for (int r = 0; r < 4; r++) {
        int m = m0 + ty * 4 + r;
        int b = m >> 6, leaf = m & 63;
        int base = (b * NSLOT + leaf) * 512;
        #pragma unroll
        for (int cc = 0; cc < 4; cc++) {
            int col = c0 + tx * 4 + cc;
            float v = acc[r][cc] + bias[col];
            if (col < 512) g_H[base + col] = v;
            else           g_C[base + col - 512] = v;
        }
    }
}

__global__ void init_state(){
    if (blockIdx.x == 0 && threadIdx.x == 0) g_barrier = 0u;
}

// ---------------------------------------------------------------------------
// Full compose for iteration 0: 63 pairs/batch -> candidate slots 64+j
// ---------------------------------------------------------------------------
__global__ __launch_bounds__(256) void compose_full(
    const float* __restrict__ wcomp, const float* __restrict__ bcomp)
{
    __shared__ float As[128][34];
    __shared__ float Ws[5][8][34];
    const int tid = threadIdx.x;
    const int tx = tid & 7, ty = tid >> 3;
    const int h0 = blockIdx.x * 8;
    const int m0 = blockIdx.y * 128;
    const int M  = BB * 63;

    const int lr = tid >> 5, kkld = tid & 31;
    int abase[16];
    #pragma unroll
    for (int t = 0; t < 16; t++) {
        int row = m0 + lr + 8 * t;
        if (row < M) { int b = row / 63; int j = row - b * 63; abase[t] = (b * NSLOT + j) * 512; }
        else abase[t] = -1;
    }

    float2 acc[4][5];
    #pragma unroll
    for (int r = 0; r < 4; r++)
        #pragma unroll
        for (int g = 0; g < 5; g++) acc[r][g] = make_float2(0.f, 0.f);

    for (int k0 = 0; k0 < 1024; k0 += 32) {
        #pragma unroll
        for (int t = 0; t < 16; t++)
            As[lr + 8 * t][kkld] = (abase[t] >= 0) ? g_H[abase[t] + k0 + kkld] : 0.f;
        #pragma unroll
        for (int t = 0; t < 5; t++) {
            int idx = tid + 256 * t;
            int g = idx >> 8, rem = idx & 255, hh = rem >> 5, kk = rem & 31;
            Ws[g][hh][kk] = wcomp[(g * 512 + h0 + hh) * 1024 + k0 + kk];
        }
        __syncthreads();
        #pragma unroll
        for (int k2 = 0; k2 < 16; k2++) {
            float2 wv[5];
            #pragma unroll
            for (int g = 0; g < 5; g++) wv[g] = ((const float2*)Ws[g][tx])[k2];
            #pragma unroll
            for (int r = 0; r < 4; r++) {
                float2 av = ((const float2*)As[ty * 4 + r])[k2];
                #pragma unroll
                for (int g = 0; g < 5; g++) ffma2(acc[r][g], av, wv[g]);
            }
        }
        __syncthreads();
    }

    int hg = h0 + tx;
    float bi  = bcomp[hg],        bfl = bcomp[512 + hg], bfr = bcomp[1024 + hg];
    float bu  = bcomp[1536 + hg], bo  = bcomp[2048 + hg];
    #pragma unroll
    for (int r = 0; r < 4; r++) {
        int row = m0 + ty * 4 + r;
        if (row >= M) continue;
        int b = row / 63, j = row - b * 63;
        int abas = (b * NSLOT + j) * 512;
        int sbas = (b * NSLOT + 64 + j) * 512;
        float cl = g_C[abas + hg], cr = g_C[abas + 512 + hg];
        float vi  = acc[r][0].x + acc[r][0].y + bi;
        float vfl = acc[r][1].x + acc[r][1].y + bfl + 1.f;
        float vfr = acc[r][2].x + acc[r][2].y + bfr + 1.f;
        float vu  = acc[r][3].x + acc[r][3].y + bu;
        float vo  = acc[r][4].x + acc[r][4].y + bo;
        float cn = cl * sigm(vfl) + cr * sigm(vfr) + tanhf(vu) * sigm(vi);
        float hn = sigm(vo) * tanhf(cn);
        g_H[sbas + hg] = hn;
        g_C[sbas + hg] = cn;
    }
}

__global__ __launch_bounds__(256) void cw_full(const float* __restrict__ q){
    int b = blockIdx.x;
    int warp = threadIdx.x >> 5, lane = threadIdx.x & 31;
    for (int j = warp; j < 63; j += 8) {
        const float* row = &g_H[(b * NSLOT + 64 + j) * 512];
        float s = 0.f;
        #pragma unroll
        for (int t = 0; t < 16; t++) s += row[lane + 32 * t] * q[lane + 32 * t];
        #pragma unroll
        for (int o = 16; o > 0; o >>= 1) s += __shfl_xor_sync(0xffffffffu, s, o);
        if (lane == 0) g_cw0[b * 63 + j] = s;
    }
}

// ---------------------------------------------------------------------------
// Persistent loop: one grid barrier/iter; float4 FMA-bound GEMM; parity cwp.
// ---------------------------------------------------------------------------
#define W_STRIDE 1028
#define A_STRIDE 68                       // floats (17 float4)
#define WRES_F   (20*W_STRIDE)
#define ASB_F    (128*A_STRIDE)
#define SMEM_BYTES ((WRES_F + 2*ASB_F)*4)

__global__ __launch_bounds__(TPB, 1) void tree_loop(
    const int* __restrict__ length, const float* __restrict__ q,
    const float* __restrict__ wcomp, const float* __restrict__ bcomp,
    float* __restrict__ out)
{
    extern __shared__ float smem[];
    float* Wres = smem;
    float* Asb0 = smem + WRES_F;
    float* Asb1 = smem + WRES_F + ASB_F;

    __shared__ unsigned char s_vh[BB][64];
    __shared__ unsigned char s_pk[BB][64];
    __shared__ float s_cw[BB][64];
    __shared__ int2  s_fresh[BB];
    __shared__ int4  s_rows[128];          // {baseL, baseR, baseStore, rowid}
    __shared__ int   s_rcnt[BB], s_roff[BB], s_len[BB];
    __shared__ int   s_nrows, s_maxlen;

    const int tid = threadIdx.x, blk = blockIdx.x;
    const int u = tid & 3, v = tid >> 2;       // GEMM/epilogue map
    const int lane = tid & 31, warp = tid >> 5;
    const int lrow = tid >> 4, lq4 = tid & 15; // loader map (rows stride 16)
    const int hg = blk * 4 + u;

    for (int idx = tid; idx < 20 * 1024; idx += TPB) {
        int r = idx >> 10, k = idx & 1023;
        Wres[r * W_STRIDE + k] = wcomp[((r >> 2) * 512 + blk * 4 + (r & 3)) * 1024 + k];
    }
    const float qv  = q[hg];
    const float bi  = bcomp[hg],        bfl = bcomp[512 + hg], bfr = bcomp[1024 + hg];
    const float bu  = bcomp[1536 + hg], bo  = bcomp[2048 + hg];

    for (int t = tid; t < BB * 64; t += TPB) {
        int b = t >> 6, j = t & 63;
        s_vh[b][j] = (unsigned char)j;
        s_pk[b][j] = (unsigned char)(64 + j);
        s_cw[b][j] = (j < 63) ? __ldcg(&g_cw0[b * 63 + j]) : -1e9f;
    }
    if (tid < BB) { s_len[tid] = length[tid]; s_fresh[tid] = make_int2(-1, -1); }
    __syncthreads();
    if (tid == 0) {
        int m = 0;
        for (int b = 0; b < BB; b++) if (s_len[b] > m) m = s_len[b];
        s_maxlen = m;
    }
    __syncthreads();
    const int maxlen = s_maxlen;

    unsigned target = 0;

    for (int i = 0; i < 63; i++) {
        if (i + 1 >= maxlen) break;        // all batches done: state frozen
        const int n = 63 - i;

        // ---- (a) fold cw partials (prefetch all loads, then reduce) ----
        if (i > 0) {
            const float* cwsrc = g_cwp[i & 1];
            float4 vbuf[16];
            int    pbuf[16];
            #pragma unroll
            for (int rr = 0; rr < 16; rr++) {
                int rid = warp + 8 * rr;
                int b = rid >> 1;
                int2 fr = s_fresh[b];
                int pidx = (rid & 1) ? fr.y : fr.x;
                pbuf[rr] = pidx;
                vbuf[rr] = (pidx >= 0)
                         ? __ldcg((const float4*)&cwsrc[rid * 128 + lane * 4])
                         : make_float4(0.f, 0.f, 0.f, 0.f);
            }
            #pragma unroll
            for (int rr = 0; rr < 16; rr++) {
                if (pbuf[rr] >= 0) {
                    float4 vv = vbuf[rr];
                    float s = (vv.x + vv.y) + (vv.z + vv.w);
                    #pragma unroll
                    for (int o = 16; o > 0; o >>= 1) s += __shfl_xor_sync(0xffffffffu, s, o);
                    if (lane == 0) s_cw[(warp + 8 * rr) >> 1][pbuf[rr]] = s;
                }
            }
        }
        __syncthreads();

        // ---- (b) select (redundant per block, deterministic) ----
        if (tid < BB) {
            int b = tid, len = s_len[b];
            int s;
            if (i + 1 >= len) s = -2;
            else if (n == 1) s = 0;
            else {
                float best = -2e9f; int bj = 0;
                for (int j = 0; j < n; j++) {
                    float val = (i + 1 + j < len) ? s_cw[b][j] : -1e9f;
                    if (val > best) { best = val; bj = j; }
                }
                s = bj;
            }
            int2 fr = make_int2(-1, -1);
            if (s >= 0) {
                s_vh[b][s] = s_pk[b][s];
                for (int j = s + 1; j < n; j++) s_vh[b][j] = s_vh[b][j + 1];
                for (int j = s; j < n - 1; j++) { s_pk[b][j] = s_pk[b][j + 1]; s_cw[b][j] = s_cw[b][j + 1]; }
                if (i < 62) {
                    if (s >= 1)     fr.x = s - 1;
                    if (s <= n - 2) fr.y = s;
                }
            }
            s_fresh[b] = fr;
            s_rcnt[b] = (fr.x >= 0) + (fr.y >= 0);
        }
        __syncthreads();
        if (tid == 0) {
            int acc = 0;
            for (int b = 0; b < BB; b++) { s_roff[b] = acc; acc += s_rcnt[b]; }
            s_nrows = acc;
        }
        __syncthreads();
        if (tid < BB) {
            int b = tid; int2 fr = s_fresh[b]; int o = s_roff[b];
            if (fr.x >= 0) {
                int p = fr.x;
                s_rows[o++] = make_int4((b * NSLOT + s_vh[b][p]) * 512,
                                        (b * NSLOT + s_vh[b][p + 1]) * 512,
                                        (b * NSLOT + s_pk[b][p]) * 512, b * 2 + 0);
            }
            if (fr.y >= 0) {
                int p = fr.y;
                s_rows[o++] = make_int4((b * NSLOT + s_vh[b][p]) * 512,
                                        (b * NSLOT + s_vh[b][p + 1]) * 512,
                                        (b * NSLOT + s_pk[b][p]) * 512, b * 2 + 1);
            }
        }
        __syncthreads();

        // ---- (c) compose fresh pairs: float4, FMA-bound, double-buffered ----
        const int nrows = s_nrows;
        if (nrows > 0) {
            // prefetch epilogue c inputs (independent of GEMM)
            float clv[2], crv[2];
            #pragma unroll
            for (int r = 0; r < 2; r++) {
                int row = v * 2 + r;
                if (row < nrows) {
                    int4 ri = s_rows[row];
                    clv[r] = __ldcg(&g_C[ri.x + hg]);
                    crv[r] = __ldcg(&g_C[ri.y + hg]);
                } else { clv[r] = 0.f; crv[r] = 0.f; }
            }

            float2 acc[2][5];
            #pragma unroll
            for (int r = 0; r < 2; r++)
                #pragma unroll
                for (int g = 0; g < 5; g++) acc[r][g] = make_float2(0.f, 0.f);

            const bool alive = (2 * v < nrows);

            // preload chunk 0 (k0=0: left side)
            float4 pf[8];
            #pragma unroll
            for (int ii = 0; ii < 8; ii++) {
                int row = lrow + 16 * ii;
                pf[ii] = (row < nrows)
                       ? __ldcg((const float4*)&g_H[s_rows[row].x + lq4 * 4])
                       : make_float4(0.f, 0.f, 0.f, 0.f);
            }
            #pragma unroll
            for (int ii = 0; ii < 8; ii++) {
                int row = lrow + 16 * ii;
                if (row < nrows) ((float4*)(Asb0 + row * A_STRIDE))[lq4] = pf[ii];
            }
            __syncthreads();

            for (int c = 0; c < 16; c++) {
                if (c < 15) {
                    int k0 = (c + 1) * 64;
                    int foff = ((c + 1) & 7) * 64 + lq4 * 4;   // within-side float offset
                    #pragma unroll
                    for (int ii = 0; ii < 8; ii++) {
                        int row = lrow + 16 * ii;
                        if (row < nrows) {
                            int4 ri = s_rows[row];
                            int basep = (k0 < 512) ? ri.x : ri.y;
                            pf[ii] = __ldcg((const float4*)&g_H[basep + foff]);
                        }
                    }
                }
                const float* A = (c & 1) ? Asb1 : Asb0;
                if (alive) {
                    #pragma unroll 8
                    for (int k4 = 0; k4 < 16; k4++) {
                        float4 wv[5];
                        #pragma unroll
                        for (int g = 0; g < 5; g++)
                            wv[g] = ((const float4*)(Wres + (g * 4 + u) * W_STRIDE))[c * 16 + k4];
                        float4 av0 = ((const float4*)(A + (v * 2) * A_STRIDE))[k4];
                        float4 av1 = ((const float4*)(A + (v * 2 + 1) * A_STRIDE))[k4];
                        #pragma unroll
                        for (int g = 0; g < 5; g++) {
                            ffma2(acc[0][g], make_float2(av0.x, av0.y), make_float2(wv[g].x, wv[g].y));
                            ffma2(acc[0][g], make_float2(av0.z, av0.w), make_float2(wv[g].z, wv[g].w));
                            ffma2(acc[1][g], make_float2(av1.x, av1.y), make_float2(wv[g].x, wv[g].y));
                            ffma2(acc[1][g], make_float2(av1.z, av1.w), make_float2(wv[g].z, wv[g].w));
                        }
                    }
                }
                if (c < 15) {
                    float* An = (c & 1) ? Asb0 : Asb1;
                    #pragma unroll
                    for (int ii = 0; ii < 8; ii++) {
                        int row = lrow + 16 * ii;
                        if (row < nrows) ((float4*)(An + row * A_STRIDE))[lq4] = pf[ii];
                    }
                }
                __syncthreads();
            }

            // ---- (d) epilogue ----
            float* cwdst = g_cwp[(i + 1) & 1];
            #pragma unroll
            for (int r = 0; r < 2; r++) {
                int row = v * 2 + r;
                float p = 0.f;
                if (row < nrows) {
                    int4 ri = s_rows[row];
                    float vi  = acc[r][0].x + acc[r][0].y + bi;
                    float vfl = acc[r][1].x + acc[r][1].y + bfl + 1.f;
                    float vfr = acc[r][2].x + acc[r][2].y + bfr + 1.f;
                    float vu  = acc[r][3].x + acc[r][3].y + bu;
                    float vo  = acc[r][4].x + acc[r][4].y + bo;
                    float cn = clv[r] * sigm(vfl) + crv[r] * sigm(vfr) + tanhf(vu) * sigm(vi);
                    float hn = sigm(vo) * tanhf(cn);
                    g_H[ri.z + hg] = hn;
                    g_C[ri.z + hg] = cn;
                    p = hn * qv;
                }
                p += __shfl_xor_sync(0xffffffffu, p, 1);
                p += __shfl_xor_sync(0xffffffffu, p, 2);
                if (row < nrows && u == 0) cwdst[s_rows[row].w * 128 + blk] = p;
            }
        }
        target += GRID; grid_barrier(target);
    }

    // ---- output: leaf 0's value slot ----
    if (blk < BB) {
        int base = (blk * NSLOT + s_vh[blk][0]) * 512;
        out[blk * 512 + tid]                  = __ldcg(&g_H[base + tid]);
        out[blk * 512 + 256 + tid]            = __ldcg(&g_H[base + 256 + tid]);
        out[BB * 512 + blk * 512 + tid]       = __ldcg(&g_C[base + tid]);
        out[BB * 512 + blk * 512 + 256 + tid] = __ldcg(&g_C[base + 256 + tid]);
    }
}

// ---------------------------------------------------------------------------
extern "C" void kernel_launch(void* const* d_in, const int* in_sizes, int n_in,
                              void* d_out, int out_size)
{
    const float* x      = (const float*)d_in[0];
    const int*   length = (const int*)  d_in[1];
    const float* w_word = (const float*)d_in[2];
    const float* b_word = (const float*)d_in[3];
    const float* w_comp = (const float*)d_in[4];
    const float* b_comp = (const float*)d_in[5];
    const float* q      = (const float*)d_in[6];
    float* out = (float*)d_out;

    static int smem_set = 0;
    if (!smem_set) {
        cudaFuncSetAttribute(tree_loop, cudaFuncAttributeMaxDynamicSharedMemorySize,
                             SMEM_BYTES);
        smem_set = 1;
    }

    word_gemm<<<dim3(16, 64), 256>>>(x, w_word, b_word);
    init_state<<<1, 32>>>();
    compose_full<<<dim3(64, 32), 256>>>(w_comp, b_comp);
    cw_full<<<BB, 256>>>(q);
    tree_loop<<<GRID, TPB, SMEM_BYTES>>>(length, q, w_comp, b_comp, out);
}

// round 8
// speedup vs baseline: 1.3582x; 1.0450x over previous
#include <cuda_runtime.h>
#include <math.h>

#define BB 64
#define GRID 128
#define TPB 256
#define NSLOT 128
#define NST (BB*NSLOT*512)

__device__ float g_H[NST];
__device__ float g_C[NST];
// vV cache, natural layout: [b][slot][side][2560] ; side0 = W_l@h, side1 = W_r@h
__device__ float g_V[BB*NSLOT*2*2560];
__device__ float g_cwp[2][128*128];   // cw partials, parity double-buffered
__device__ float g_cw0[BB*63];
__device__ unsigned g_bar[4];

__device__ __forceinline__ float sigm(float x){ return 1.0f/(1.0f+expf(-x)); }

__device__ __forceinline__ void ffma2(float2 &acc, float2 a, float2 b){
    asm("fma.rn.f32x2 %0, %1, %2, %0;"
        : "+l"(reinterpret_cast<unsigned long long&>(acc))
        : "l"(reinterpret_cast<unsigned long long&>(a)),
          "l"(reinterpret_cast<unsigned long long&>(b)));
}

// release/acquire grid barrier, 4-way split counters (less L2 atomic serialization)
__device__ __forceinline__ void grid_barrier(unsigned target){
    __syncthreads();
    if (threadIdx.x == 0){
        asm volatile("red.release.gpu.global.add.u32 [%0], 1;"
                     :: "l"(&g_bar[blockIdx.x & 3]) : "memory");
        unsigned v0, v1, v2, v3;
        do {
            asm volatile("ld.acquire.gpu.global.u32 %0, [%1];" : "=r"(v0) : "l"(&g_bar[0]) : "memory");
            asm volatile("ld.acquire.gpu.global.u32 %0, [%1];" : "=r"(v1) : "l"(&g_bar[1]) : "memory");
            asm volatile("ld.acquire.gpu.global.u32 %0, [%1];" : "=r"(v2) : "l"(&g_bar[2]) : "memory");
            asm volatile("ld.acquire.gpu.global.u32 %0, [%1];" : "=r"(v3) : "l"(&g_bar[3]) : "memory");
        } while (v0 + v1 + v2 + v3 < target);
    }
    __syncthreads();
}

// ---------------------------------------------------------------------------
__global__ __launch_bounds__(256) void word_gemm(
    const float* __restrict__ x, const float* __restrict__ w,
    const float* __restrict__ bias)
{
    __shared__ float As[64][33];
    __shared__ float Ws[64][33];
    int tid = threadIdx.x;
    int tx = tid & 15, ty = tid >> 4;
    int m0 = blockIdx.y * 64;
    int c0 = blockIdx.x * 64;
    float acc[4][4] = {};

    for (int k0 = 0; k0 < 512; k0 += 32) {
        #pragma unroll
        for (int t = tid; t < 64 * 32; t += 256) {
            int r = t >> 5, kk = t & 31;
            As[r][kk] = x[(m0 + r) * 512 + k0 + kk];
            Ws[r][kk] = w[(c0 + r) * 512 + k0 + kk];
        }
        __syncthreads();
        #pragma unroll
        for (int kk = 0; kk < 32; kk++) {
            float a[4], b[4];
            #pragma unroll
            for (int r = 0; r < 4; r++) a[r] = As[ty * 4 + r][kk];
            #pragma unroll
            for (int cc = 0; cc < 4; cc++) b[cc] = Ws[tx * 4 + cc][kk];
            #pragma unroll
            for (int r = 0; r < 4; r++)
                #pragma unroll
                for (int cc = 0; cc < 4; cc++)
                    acc[r][cc] += a[r] * b[cc];
        }
        __syncthreads();
    }
    #pragma unroll
    for (int r = 0; r < 4; r++) {
        int m = m0 + ty * 4 + r;
        int b = m >> 6, leaf = m & 63;
        int base = (b * NSLOT + leaf) * 512;
        #pragma unroll
        for (int cc = 0; cc < 4; cc++) {
            int col = c0 + tx * 4 + cc;
            float v = acc[r][cc] + bias[col];
            if (col < 512) g_H[base + col] = v;
            else           g_C[base + col - 512] = v;
        }
    }
}

__global__ void init_state(){
    if (blockIdx.x == 0 && threadIdx.x < 4) g_bar[threadIdx.x] = 0u;
}

// ---------------------------------------------------------------------------
// vV for all 4096 leaf nodes: vV[node][side] = W_side @ h[node]  (no bias)
// grid: x = 64 hd-groups * 2 sides (128), y = 32 row groups of 128
// ---------------------------------------------------------------------------
__global__ __launch_bounds__(256) void vv_full(const float* __restrict__ wcomp)
{
    __shared__ float As[128][34];
    __shared__ float Ws[5][8][34];
    const int tid = threadIdx.x;
    const int tx = tid & 7, ty = tid >> 3;
    const int side = blockIdx.x & 1;
    const int h0 = (blockIdx.x >> 1) * 8;
    const int m0 = blockIdx.y * 128;       // rows 0..4095, row = b*64 + leaf

    const int lr = tid >> 5, kkld = tid & 31;
    int abase[16];
    #pragma unroll
    for (int t = 0; t < 16; t++) {
        int row = m0 + lr + 8 * t;
        int b = row >> 6, leaf = row & 63;
        abase[t] = (b * NSLOT + leaf) * 512;
    }

    float2 acc[4][5];
    #pragma unroll
    for (int r = 0; r < 4; r++)
        #pragma unroll
        for (int g = 0; g < 5; g++) acc[r][g] = make_float2(0.f, 0.f);

    for (int k0 = 0; k0 < 512; k0 += 32) {
        #pragma unroll
        for (int t = 0; t < 16; t++)
            As[lr + 8 * t][kkld] = g_H[abase[t] + k0 + kkld];
        #pragma unroll
        for (int t = 0; t < 5; t++) {
            int idx = tid + 256 * t;
            int g = idx >> 8, rem = idx & 255, hh = rem >> 5, kk = rem & 31;
            Ws[g][hh][kk] = wcomp[(g * 512 + h0 + hh) * 1024 + side * 512 + k0 + kk];
        }
        __syncthreads();
        #pragma unroll
        for (int k2 = 0; k2 < 16; k2++) {
            float2 wv[5];
            #pragma unroll
            for (int g = 0; g < 5; g++) wv[g] = ((const float2*)Ws[g][tx])[k2];
            #pragma unroll
            for (int r = 0; r < 4; r++) {
                float2 av = ((const float2*)As[ty * 4 + r])[k2];
                #pragma unroll
                for (int g = 0; g < 5; g++) ffma2(acc[r][g], av, wv[g]);
            }
        }
        __syncthreads();
    }

    #pragma unroll
    for (int r = 0; r < 4; r++) {
        int row = m0 + ty * 4 + r;
        int b = row >> 6, leaf = row & 63;
        int vbase = ((b * NSLOT + leaf) * 2 + side) * 2560;
        #pragma unroll
        for (int g = 0; g < 5; g++)
            g_V[vbase + g * 512 + h0 + tx] = acc[r][g].x + acc[r][g].y;
    }
}

// ---------------------------------------------------------------------------
// Iter-0 candidates: pair (j, j+1) -> slot 64+j, h/c + cw0.  4032 blocks.
// ---------------------------------------------------------------------------
__global__ __launch_bounds__(256) void pair_epi(
    const float* __restrict__ bcomp, const float* __restrict__ q)
{
    __shared__ float red[8];
    int pb = blockIdx.x;
    int b = pb / 63, j = pb - b * 63;
    int nl = b * NSLOT + j, nr = nl + 1, ns = b * NSLOT + 64 + j;
    int tid = threadIdx.x, lane = tid & 31, warp = tid >> 5;
    float p = 0.f;
    #pragma unroll
    for (int half = 0; half < 2; half++) {
        int hd = tid + 256 * half;
        float vg[5];
        #pragma unroll
        for (int g = 0; g < 5; g++)
            vg[g] = __ldcg(&g_V[(nl * 2 + 0) * 2560 + g * 512 + hd])
                  + __ldcg(&g_V[(nr * 2 + 1) * 2560 + g * 512 + hd])
                  + bcomp[g * 512 + hd];
        float cl = __ldcg(&g_C[nl * 512 + hd]), cr = __ldcg(&g_C[nr * 512 + hd]);
        float cn = cl * sigm(vg[1] + 1.f) + cr * sigm(vg[2] + 1.f)
                 + tanhf(vg[3]) * sigm(vg[0]);
        float hn = sigm(vg[4]) * tanhf(cn);
        g_H[ns * 512 + hd] = hn;
        g_C[ns * 512 + hd] = cn;
        p += hn * q[hd];
    }
    #pragma unroll
    for (int o = 16; o > 0; o >>= 1) p += __shfl_xor_sync(0xffffffffu, p, o);
    if (lane == 0) red[warp] = p;
    __syncthreads();
    if (tid == 0) {
        float s = 0.f;
        #pragma unroll
        for (int w = 0; w < 8; w++) s += red[w];
        g_cw0[b * 63 + j] = s;
    }
}

// ---------------------------------------------------------------------------
// Persistent loop: per iter: fold cw, select, vV-GEMM of merged node (M=64,
// K=512, 40 outs/block), epilogue = vV_l + vV_r -> gates, one barrier.
// ---------------------------------------------------------------------------
#define W_STRIDE 516
#define A_STRIDE 68
#define WRES_F   (40*W_STRIDE)
#define ASB_F    (64*A_STRIDE)
#define SVN_F    (64*40)
#define SMEM_BYTES ((WRES_F + 2*ASB_F + SVN_F)*4)

__global__ __launch_bounds__(TPB, 1) void tree_loop(
    const int* __restrict__ length, const float* __restrict__ q,
    const float* __restrict__ wcomp, const float* __restrict__ bcomp,
    float* __restrict__ out)
{
    extern __shared__ float smem[];
    float* Wres  = smem;                       // 40 x 516 (r2 = side*20+g*4+hgoff)
    float* Asb0  = smem + WRES_F;              // 64 x 68
    float* Asb1  = smem + WRES_F + ASB_F;
    float* sVnew = smem + WRES_F + 2*ASB_F;    // [64 batches][40]

    __shared__ unsigned char s_vh[BB][64];
    __shared__ unsigned char s_pk[BB][64];
    __shared__ float s_cw[BB][64];
    __shared__ int2  s_fresh[BB];
    __shared__ int   s_nodeidx[BB];            // b*NSLOT+mergedslot or -1
    __shared__ int4  s_rows[128];              // {nodeL, nodeR, nodeStore, rowid}
    __shared__ unsigned char s_rb[128], s_rln[128], s_rrn[128];
    __shared__ int   s_rcnt[BB], s_roff[BB], s_len[BB];
    __shared__ int   s_nrows, s_maxlen;

    const int tid = threadIdx.x, blk = blockIdx.x;
    const int u = tid & 3, v = tid >> 2;       // v: batch row (GEMM) / row group (epi)
    const int lane = tid & 31, warp = tid >> 5;
    const int hg = blk * 4 + u;

    // resident W slice: 40 rows x 512
    for (int idx = tid; idx < 40 * 512; idx += TPB) {
        int r2 = idx >> 9, k = idx & 511;
        int side = r2 / 20, rem = r2 % 20, g = rem >> 2, hgo = rem & 3;
        Wres[r2 * W_STRIDE + k] = wcomp[(g * 512 + blk * 4 + hgo) * 1024 + side * 512 + k];
    }
    const float qv  = q[hg];
    const float bi  = bcomp[hg],        bfl = bcomp[512 + hg], bfr = bcomp[1024 + hg];
    const float bu  = bcomp[1536 + hg], bo  = bcomp[2048 + hg];

    for (int t = tid; t < BB * 64; t += TPB) {
        int b = t >> 6, j = t & 63;
        s_vh[b][j] = (unsigned char)j;
        s_pk[b][j] = (unsigned char)(64 + j);
        s_cw[b][j] = (j < 63) ? __ldcg(&g_cw0[b * 63 + j]) : -1e9f;
    }
    if (tid < BB) { s_len[tid] = length[tid]; s_fresh[tid] = make_int2(-1, -1); }
    __syncthreads();
    if (tid == 0) {
        int m = 0;
        for (int b = 0; b < BB; b++) if (s_len[b] > m) m = s_len[b];
        s_maxlen = m;
    }
    __syncthreads();
    const int maxlen = s_maxlen;

    unsigned target = 0;

    for (int i = 0; i < 63; i++) {
        if (i + 1 >= maxlen) break;
        const int n = 63 - i;

        // ---- (a) fold cw partials (prefetch, then reduce) ----
        if (i > 0) {
            const float* cwsrc = g_cwp[i & 1];
            float4 vbuf[16];
            int    pbuf[16];
            #pragma unroll
            for (int rr = 0; rr < 16; rr++) {
                int rid = warp + 8 * rr;
                int b = rid >> 1;
                int2 fr = s_fresh[b];
                int pidx = (rid & 1) ? fr.y : fr.x;
                pbuf[rr] = pidx;
                vbuf[rr] = (pidx >= 0)
                         ? __ldcg((const float4*)&cwsrc[rid * 128 + lane * 4])
                         : make_float4(0.f, 0.f, 0.f, 0.f);
            }
            #pragma unroll
            for (int rr = 0; rr < 16; rr++) {
                if (pbuf[rr] >= 0) {
                    float4 vv = vbuf[rr];
                    float s = (vv.x + vv.y) + (vv.z + vv.w);
                    #pragma unroll
                    for (int o = 16; o > 0; o >>= 1) s += __shfl_xor_sync(0xffffffffu, s, o);
                    if (lane == 0) s_cw[(warp + 8 * rr) >> 1][pbuf[rr]] = s;
                }
            }
        }
        __syncthreads();

        // ---- (b) select (redundant per block, deterministic) ----
        if (tid < BB) {
            int b = tid, len = s_len[b];
            int s;
            if (i + 1 >= len) s = -2;
            else if (n == 1) s = 0;
            else {
                float best = -2e9f; int bj = 0;
                for (int j = 0; j < n; j++) {
                    float val = (i + 1 + j < len) ? s_cw[b][j] : -1e9f;
                    if (val > best) { best = val; bj = j; }
                }
                s = bj;
            }
            int merged = -1;
            int2 fr = make_int2(-1, -1);
            if (s >= 0) {
                merged = s_pk[b][s];
                s_vh[b][s] = (unsigned char)merged;
                for (int j = s + 1; j < n; j++) s_vh[b][j] = s_vh[b][j + 1];
                for (int j = s; j < n - 1; j++) { s_pk[b][j] = s_pk[b][j + 1]; s_cw[b][j] = s_cw[b][j + 1]; }
                if (i < 62) {
                    if (s >= 1)     fr.x = s - 1;
                    if (s <= n - 2) fr.y = s;
                }
            }
            s_fresh[b] = fr;
            s_nodeidx[b] = (merged >= 0 && i < 62) ? (b * NSLOT + merged) : -1;
            s_rcnt[b] = (fr.x >= 0) + (fr.y >= 0);
        }
        __syncthreads();
        if (tid == 0) {
            int acc = 0;
            for (int b = 0; b < BB; b++) { s_roff[b] = acc; acc += s_rcnt[b]; }
            s_nrows = acc;
        }
        __syncthreads();
        if (tid < BB) {
            int b = tid; int2 fr = s_fresh[b]; int o = s_roff[b];
            if (fr.x >= 0) {                  // (old, NEW)
                int p = fr.x;
                s_rows[o] = make_int4(b * NSLOT + s_vh[b][p], b * NSLOT + s_vh[b][p + 1],
                                      b * NSLOT + s_pk[b][p], b * 2 + 0);
                s_rb[o] = (unsigned char)b; s_rln[o] = 0; s_rrn[o] = 1; o++;
            }
            if (fr.y >= 0) {                  // (NEW, old)
                int p = fr.y;
                s_rows[o] = make_int4(b * NSLOT + s_vh[b][p], b * NSLOT + s_vh[b][p + 1],
                                      b * NSLOT + s_pk[b][p], b * 2 + 1);
                s_rb[o] = (unsigned char)b; s_rln[o] = 1; s_rrn[o] = 0; o++;
            }
        }
        __syncthreads();

        const int nrows = s_nrows;

        // ---- prefetch epilogue operands (hidden under GEMM) ----
        float pvl[2][5], pvr[2][5], clv[2], crv[2];
        #pragma unroll
        for (int r = 0; r < 2; r++) {
            int row = v * 2 + r;
            if (row < nrows) {
                int4 ri = s_rows[row];
                clv[r] = __ldcg(&g_C[ri.x * 512 + hg]);
                crv[r] = __ldcg(&g_C[ri.y * 512 + hg]);
                if (!s_rln[row]) {
                    #pragma unroll
                    for (int g = 0; g < 5; g++)
                        pvl[r][g] = __ldcg(&g_V[(ri.x * 2 + 0) * 2560 + g * 512 + hg]);
                }
                if (!s_rrn[row]) {
                    #pragma unroll
                    for (int g = 0; g < 5; g++)
                        pvr[r][g] = __ldcg(&g_V[(ri.y * 2 + 1) * 2560 + g * 512 + hg]);
                }
            } else { clv[r] = 0.f; crv[r] = 0.f; }
        }

        // ---- (c) vV GEMM for merged nodes: M=64 rows, K=512, 40 outs ----
        if (i < 62) {
            const int ni = s_nodeidx[v];       // v = batch = loader row
            float2 acc[10];
            #pragma unroll
            for (int a = 0; a < 10; a++) acc[a] = make_float2(0.f, 0.f);

            float4 pf[4];
            #pragma unroll
            for (int t = 0; t < 4; t++)
                pf[t] = (ni >= 0)
                      ? __ldcg((const float4*)&g_H[ni * 512 + (u + 4 * t) * 4])
                      : make_float4(0.f, 0.f, 0.f, 0.f);
            #pragma unroll
            for (int t = 0; t < 4; t++)
                ((float4*)(Asb0 + v * A_STRIDE))[u + 4 * t] = pf[t];
            __syncthreads();

            for (int c = 0; c < 8; c++) {
                if (c < 7) {
                    int foff = (c + 1) * 64 + (u + 4 * (0)) * 4;  // base; per t below
                    #pragma unroll
                    for (int t = 0; t < 4; t++)
                        pf[t] = (ni >= 0)
                              ? __ldcg((const float4*)&g_H[ni * 512 + (c + 1) * 64 + (u + 4 * t) * 4])
                              : make_float4(0.f, 0.f, 0.f, 0.f);
                    (void)foff;
                }
                const float* A = (c & 1) ? Asb1 : Asb0;
                if (ni >= 0) {
                    #pragma unroll
                    for (int k4 = 0; k4 < 16; k4++) {
                        float4 av = ((const float4*)(A + v * A_STRIDE))[k4];
                        float2 alo = make_float2(av.x, av.y);
                        float2 ahi = make_float2(av.z, av.w);
                        #pragma unroll
                        for (int a = 0; a < 10; a++) {
                            int r2 = (a >= 5 ? 20 : 0) + (a % 5) * 4 + u;
                            float4 wv = ((const float4*)(Wres + r2 * W_STRIDE))[c * 16 + k4];
                            ffma2(acc[a], alo, make_float2(wv.x, wv.y));
                            ffma2(acc[a], ahi, make_float2(wv.z, wv.w));
                        }
                    }
                }
                if (c < 7) {
                    float* An = (c & 1) ? Asb0 : Asb1;
                    #pragma unroll
                    for (int t = 0; t < 4; t++)
                        ((float4*)(An + v * A_STRIDE))[u + 4 * t] = pf[t];
                }
                __syncthreads();
            }

            if (ni >= 0) {
                #pragma unroll
                for (int a = 0; a < 10; a++) {
                    int side = (a >= 5), g = a % 5;
                    float val = acc[a].x + acc[a].y;
                    sVnew[v * 40 + side * 20 + g * 4 + u] = val;
                    g_V[(ni * 2 + side) * 2560 + g * 512 + hg] = val;
                }
            }
            __syncthreads();
        }

        // ---- (d) epilogue: gates from vV sums ----
        if (nrows > 0) {
            float* cwdst = g_cwp[(i + 1) & 1];
            #pragma unroll
            for (int r = 0; r < 2; r++) {
                int row = v * 2 + r;
                float p = 0.f;
                if (row < nrows) {
                    int bb = s_rb[row];
                    float vg[5];
                    #pragma unroll
                    for (int g = 0; g < 5; g++) {
                        float L = s_rln[row] ? sVnew[bb * 40 + g * 4 + u]      : pvl[r][g];
                        float R = s_rrn[row] ? sVnew[bb * 40 + 20 + g * 4 + u] : pvr[r][g];
                        vg[g] = L + R;
                    }
                    float cn = clv[r] * sigm(vg[1] + bfl + 1.f) + crv[r] * sigm(vg[2] + bfr + 1.f)
                             + tanhf(vg[3] + bu) * sigm(vg[0] + bi);
                    float hn = sigm(vg[4] + bo) * tanhf(cn);
                    int nst = s_rows[row].z;
                    g_H[nst * 512 + hg] = hn;
                    g_C[nst * 512 + hg] = cn;
                    p = hn * qv;
                }
                p += __shfl_xor_sync(0xffffffffu, p, 1);
                p += __shfl_xor_sync(0xffffffffu, p, 2);
                if (row < nrows && u == 0) cwdst[s_rows[row].w * 128 + blk] = p;
            }
        }
        target += GRID; grid_barrier(target);
    }

    // ---- output: leaf 0's value slot ----
    if (blk < BB) {
        int base = (blk * NSLOT + s_vh[blk][0]) * 512;
        out[blk * 512 + tid]                  = __ldcg(&g_H[base + tid]);
        out[blk * 512 + 256 + tid]            = __ldcg(&g_H[base + 256 + tid]);
        out[BB * 512 + blk * 512 + tid]       = __ldcg(&g_C[base + tid]);
        out[BB * 512 + blk * 512 + 256 + tid] = __ldcg(&g_C[base + 256 + tid]);
    }
}

// ---------------------------------------------------------------------------
extern "C" void kernel_launch(void* const* d_in, const int* in_sizes, int n_in,
                              void* d_out, int out_size)
{
    const float* x      = (const float*)d_in[0];
    const int*   length = (const int*)  d_in[1];
    const float* w_word = (const float*)d_in[2];
    const float* b_word = (const float*)d_in[3];
    const float* w_comp = (const float*)d_in[4];
    const float* b_comp = (const float*)d_in[5];
    const float* q      = (const float*)d_in[6];
    float* out = (float*)d_out;

    static int smem_set = 0;
    if (!smem_set) {
        cudaFuncSetAttribute(tree_loop, cudaFuncAttributeMaxDynamicSharedMemorySize,
                             SMEM_BYTES);
        smem_set = 1;
    }

    word_gemm<<<dim3(16, 64), 256>>>(x, w_word, b_word);
    init_state<<<1, 32>>>();
    vv_full<<<dim3(128, 32), 256>>>(w_comp);
    pair_epi<<<4032, 256>>>(b_comp, q);
    tree_loop<<<GRID, TPB, SMEM_BYTES>>>(length, q, w_comp, b_comp, out);
}

// round 9
// speedup vs baseline: 1.4060x; 1.0352x over previous
#include <cuda_runtime.h>
#include <math.h>

#define BB 64
#define GRID 128
#define TPB 256
#define NSLOT 128
#define NST (BB*NSLOT*512)

__device__ float g_H[NST];
__device__ float g_C[NST];
// vV cache: [b][slot][side][2560] ; side0 = W_l@h, side1 = W_r@h
__device__ float g_V[BB*NSLOT*2*2560];
__device__ float g_cwp[2][128*128];   // cw partials, parity double-buffered
__device__ float g_cw0[BB*63];
__device__ unsigned g_bar[4];

__device__ __forceinline__ float sigm(float x){ return 1.0f/(1.0f+expf(-x)); }

__device__ __forceinline__ void ffma2(float2 &acc, float2 a, float2 b){
    asm("fma.rn.f32x2 %0, %1, %2, %0;"
        : "+l"(reinterpret_cast<unsigned long long&>(acc))
        : "l"(reinterpret_cast<unsigned long long&>(a)),
          "l"(reinterpret_cast<unsigned long long&>(b)));
}

__device__ __forceinline__ void grid_barrier(unsigned target){
    __syncthreads();
    if (threadIdx.x == 0){
        asm volatile("red.release.gpu.global.add.u32 [%0], 1;"
                     :: "l"(&g_bar[blockIdx.x & 3]) : "memory");
        unsigned v0, v1, v2, v3;
        do {
            asm volatile("ld.acquire.gpu.global.u32 %0, [%1];" : "=r"(v0) : "l"(&g_bar[0]) : "memory");
            asm volatile("ld.acquire.gpu.global.u32 %0, [%1];" : "=r"(v1) : "l"(&g_bar[1]) : "memory");
            asm volatile("ld.acquire.gpu.global.u32 %0, [%1];" : "=r"(v2) : "l"(&g_bar[2]) : "memory");
            asm volatile("ld.acquire.gpu.global.u32 %0, [%1];" : "=r"(v3) : "l"(&g_bar[3]) : "memory");
        } while (v0 + v1 + v2 + v3 < target);
    }
    __syncthreads();
}

// noop first so ncu (-s 5 -c 1) captures tree_loop as launch #6
__global__ void noop_k(){}

// ---------------------------------------------------------------------------
// Word GEMM (f32x2 over column pairs, transposed W tile): ~2x round-8 speed
// ---------------------------------------------------------------------------
__global__ __launch_bounds__(256) void word_gemm(
    const float* __restrict__ x, const float* __restrict__ w,
    const float* __restrict__ bias)
{
    __shared__ float As[64][33];
    __shared__ float Wt[32][68];   // [kk][col], padded
    int tid = threadIdx.x;
    int tx = tid & 15, ty = tid >> 4;
    int m0 = blockIdx.y * 64;
    int c0 = blockIdx.x * 64;
    const int lr = tid >> 5, kkld = tid & 31;

    float2 acc[4][2];
    #pragma unroll
    for (int r = 0; r < 4; r++){ acc[r][0] = make_float2(0.f,0.f); acc[r][1] = make_float2(0.f,0.f); }

    for (int k0 = 0; k0 < 512; k0 += 32) {
        #pragma unroll
        for (int t = 0; t < 8; t++) {
            int r = lr + 8 * t;
            As[r][kkld] = x[(m0 + r) * 512 + k0 + kkld];
            Wt[kkld][r] = w[(c0 + r) * 512 + k0 + kkld];
        }
        __syncthreads();
        #pragma unroll
        for (int kk = 0; kk < 32; kk++) {
            float4 wv = *(const float4*)&Wt[kk][tx * 4];
            #pragma unroll
            for (int r = 0; r < 4; r++) {
                float a = As[ty * 4 + r][kk];
                ffma2(acc[r][0], make_float2(a, a), make_float2(wv.x, wv.y));
                ffma2(acc[r][1], make_float2(a, a), make_float2(wv.z, wv.w));
            }
        }
        __syncthreads();
    }
    #pragma unroll
    for (int r = 0; r < 4; r++) {
        int m = m0 + ty * 4 + r;
        int b = m >> 6, leaf = m & 63;
        int base = (b * NSLOT + leaf) * 512;
        #pragma unroll
        for (int c2 = 0; c2 < 2; c2++) {
            #pragma unroll
            for (int e = 0; e < 2; e++) {
                int col = c0 + tx * 4 + c2 * 2 + e;
                float v = (e ? acc[r][c2].y : acc[r][c2].x) + bias[col];
                if (col < 512) g_H[base + col] = v;
                else           g_C[base + col - 512] = v;
            }
        }
    }
}

__global__ void init_state(){
    if (blockIdx.x == 0 && threadIdx.x < 4) g_bar[threadIdx.x] = 0u;
}

// ---------------------------------------------------------------------------
// vV for all 4096 leaf nodes (float4 smem reads -> FMA-bound)
// ---------------------------------------------------------------------------
__global__ __launch_bounds__(256) void vv_full(const float* __restrict__ wcomp)
{
    __shared__ float As[128][36];
    __shared__ float Ws[5][8][36];
    const int tid = threadIdx.x;
    const int tx = tid & 7, ty = tid >> 3;
    const int side = blockIdx.x & 1;
    const int h0 = (blockIdx.x >> 1) * 8;
    const int m0 = blockIdx.y * 128;

    const int lr = tid >> 5, kkld = tid & 31;
    int abase[16];
    #pragma unroll
    for (int t = 0; t < 16; t++) {
        int row = m0 + lr + 8 * t;
        int b = row >> 6, leaf = row & 63;
        abase[t] = (b * NSLOT + leaf) * 512;
    }

    float2 acc[4][5];
    #pragma unroll
    for (int r = 0; r < 4; r++)
        #pragma unroll
        for (int g = 0; g < 5; g++) acc[r][g] = make_float2(0.f, 0.f);

    for (int k0 = 0; k0 < 512; k0 += 32) {
        #pragma unroll
        for (int t = 0; t < 16; t++)
            As[lr + 8 * t][kkld] = g_H[abase[t] + k0 + kkld];
        #pragma unroll
        for (int t = 0; t < 5; t++) {
            int idx = tid + 256 * t;
            int g = idx >> 8, rem = idx & 255, hh = rem >> 5, kk = rem & 31;
            Ws[g][hh][kk] = wcomp[(g * 512 + h0 + hh) * 1024 + side * 512 + k0 + kk];
        }
        __syncthreads();
        #pragma unroll
        for (int k4 = 0; k4 < 8; k4++) {
            float4 wv[5];
            #pragma unroll
            for (int g = 0; g < 5; g++) wv[g] = ((const float4*)Ws[g][tx])[k4];
            #pragma unroll
            for (int r = 0; r < 4; r++) {
                float4 av = ((const float4*)As[ty * 4 + r])[k4];
                #pragma unroll
                for (int g = 0; g < 5; g++) {
                    ffma2(acc[r][g], make_float2(av.x, av.y), make_float2(wv[g].x, wv[g].y));
                    ffma2(acc[r][g], make_float2(av.z, av.w), make_float2(wv[g].z, wv[g].w));
                }
            }
        }
        __syncthreads();
    }

    #pragma unroll
    for (int r = 0; r < 4; r++) {
        int row = m0 + ty * 4 + r;
        int b = row >> 6, leaf = row & 63;
        int vbase = ((b * NSLOT + leaf) * 2 + side) * 2560;
        #pragma unroll
        for (int g = 0; g < 5; g++)
            g_V[vbase + g * 512 + h0 + tx] = acc[r][g].x + acc[r][g].y;
    }
}

// ---------------------------------------------------------------------------
// Iter-0 candidates from vV: h/c + cw0.  4032 blocks.
// ---------------------------------------------------------------------------
__global__ __launch_bounds__(256) void pair_epi(
    const float* __restrict__ bcomp, const float* __restrict__ q)
{
    __shared__ float red[8];
    int pb = blockIdx.x;
    int b = pb / 63, j = pb - b * 63;
    int nl = b * NSLOT + j, nr = nl + 1, ns = b * NSLOT + 64 + j;
    int tid = threadIdx.x, lane = tid & 31, warp = tid >> 5;
    float p = 0.f;
    #pragma unroll
    for (int half = 0; half < 2; half++) {
        int hd = tid + 256 * half;
        float vg[5];
        #pragma unroll
        for (int g = 0; g < 5; g++)
            vg[g] = __ldcg(&g_V[(nl * 2 + 0) * 2560 + g * 512 + hd])
                  + __ldcg(&g_V[(nr * 2 + 1) * 2560 + g * 512 + hd])
                  + bcomp[g * 512 + hd];
        float cl = __ldcg(&g_C[nl * 512 + hd]), cr = __ldcg(&g_C[nr * 512 + hd]);
        float cn = cl * sigm(vg[1] + 1.f) + cr * sigm(vg[2] + 1.f)
                 + tanhf(vg[3]) * sigm(vg[0]);
        float hn = sigm(vg[4]) * tanhf(cn);
        g_H[ns * 512 + hd] = hn;
        g_C[ns * 512 + hd] = cn;
        p += hn * q[hd];
    }
    #pragma unroll
    for (int o = 16; o > 0; o >>= 1) p += __shfl_xor_sync(0xffffffffu, p, o);
    if (lane == 0) red[warp] = p;
    __syncthreads();
    if (tid == 0) {
        float s = 0.f;
        #pragma unroll
        for (int w = 0; w < 8; w++) s += red[w];
        g_cw0[b * 63 + j] = s;
    }
}

// ---------------------------------------------------------------------------
// Persistent loop
// ---------------------------------------------------------------------------
#define W_STRIDE 516
#define A_STRIDE 68
#define WRES_F   (40*W_STRIDE)
#define ASB_F    (64*A_STRIDE)
#define SVN_F    (64*40)
#define SMEM_BYTES ((WRES_F + 2*ASB_F + SVN_F)*4)

__global__ __launch_bounds__(TPB, 1) void tree_loop(
    const int* __restrict__ length, const float* __restrict__ q,
    const float* __restrict__ wcomp, const float* __restrict__ bcomp,
    float* __restrict__ out)
{
    extern __shared__ float smem[];
    float* Wres  = smem;
    float* Asb0  = smem + WRES_F;
    float* Asb1  = smem + WRES_F + ASB_F;
    float* sVnew = smem + WRES_F + 2*ASB_F;

    __shared__ unsigned char s_vh[BB][64];
    __shared__ unsigned char s_pk[BB][64];
    __shared__ float s_cw[BB][64];
    __shared__ int2  s_fresh[BB];
    __shared__ int   s_sel[BB];
    __shared__ int   s_nodeidx[BB];
    __shared__ int4  s_rows[128];
    __shared__ unsigned char s_rb[128], s_rln[128], s_rrn[128];
    __shared__ int   s_rcnt[BB], s_roff[BB], s_len[BB];
    __shared__ int   s_nrows, s_maxlen;

    const int tid = threadIdx.x, blk = blockIdx.x;
    const int u = tid & 3, v = tid >> 2;
    const int lane = tid & 31, warp = tid >> 5;
    const int hg = blk * 4 + u;

    for (int idx = tid; idx < 40 * 512; idx += TPB) {
        int r2 = idx >> 9, k = idx & 511;
        int side = r2 / 20, rem = r2 % 20, g = rem >> 2, hgo = rem & 3;
        Wres[r2 * W_STRIDE + k] = wcomp[(g * 512 + blk * 4 + hgo) * 1024 + side * 512 + k];
    }
    const float qv  = q[hg];
    const float bi  = bcomp[hg],        bfl = bcomp[512 + hg], bfr = bcomp[1024 + hg];
    const float bu  = bcomp[1536 + hg], bo  = bcomp[2048 + hg];

    for (int t = tid; t < BB * 64; t += TPB) {
        int b = t >> 6, j = t & 63;
        s_vh[b][j] = (unsigned char)j;
        s_pk[b][j] = (unsigned char)(64 + j);
        s_cw[b][j] = (j < 63) ? __ldcg(&g_cw0[b * 63 + j]) : -1e9f;
    }
    if (tid < BB) { s_len[tid] = length[tid]; s_fresh[tid] = make_int2(-1, -1); }
    __syncthreads();
    if (tid == 0) {
        int m = 0;
        for (int b = 0; b < BB; b++) if (s_len[b] > m) m = s_len[b];
        s_maxlen = m;
    }
    __syncthreads();
    const int maxlen = s_maxlen;

    unsigned target = 0;

    for (int i = 0; i < 63; i++) {
        if (i + 1 >= maxlen) break;
        const int n = 63 - i;

        // ---- (a) fold cw partials ----
        if (i > 0) {
            const float* cwsrc = g_cwp[i & 1];
            float4 vbuf[16];
            int    pbuf[16];
            #pragma unroll
            for (int rr = 0; rr < 16; rr++) {
                int rid = warp + 8 * rr;
                int b = rid >> 1;
                int2 fr = s_fresh[b];
                int pidx = (rid & 1) ? fr.y : fr.x;
                pbuf[rr] = pidx;
                vbuf[rr] = (pidx >= 0)
                         ? __ldcg((const float4*)&cwsrc[rid * 128 + lane * 4])
                         : make_float4(0.f, 0.f, 0.f, 0.f);
            }
            #pragma unroll
            for (int rr = 0; rr < 16; rr++) {
                if (pbuf[rr] >= 0) {
                    float4 vv = vbuf[rr];
                    float s = (vv.x + vv.y) + (vv.z + vv.w);
                    #pragma unroll
                    for (int o = 16; o > 0; o >>= 1) s += __shfl_xor_sync(0xffffffffu, s, o);
                    if (lane == 0) s_cw[(warp + 8 * rr) >> 1][pbuf[rr]] = s;
                }
            }
        }
        __syncthreads();

        // ---- (b1) select decision (no shifts) ----
        if (tid < BB) {
            int b = tid, len = s_len[b];
            int s;
            if (i + 1 >= len) s = -2;
            else if (n == 1) s = 0;
            else {
                float best = -2e9f; int bj = 0;
                for (int j = 0; j < n; j++) {
                    float val = (i + 1 + j < len) ? s_cw[b][j] : -1e9f;
                    if (val > best) { best = val; bj = j; }
                }
                s = bj;
            }
            s_sel[b] = s;
            int merged = -1;
            int2 fr = make_int2(-1, -1);
            if (s >= 0) {
                merged = s_pk[b][s];
                if (i < 62) {
                    if (s >= 1)     fr.x = s - 1;
                    if (s <= n - 2) fr.y = s;
                }
            }
            s_fresh[b] = fr;
            s_nodeidx[b] = (merged >= 0 && i < 62) ? (b * NSLOT + merged) : -1;
            s_rcnt[b] = (fr.x >= 0) + (fr.y >= 0);
        }
        __syncthreads();

        // ---- (b2) parallel shift: read-all, sync, write-all ----
        {
            unsigned char nvh[16], npk[16];
            float ncw[16];
            #pragma unroll
            for (int t2 = 0; t2 < 16; t2++) {
                int t = tid + 256 * t2;
                int b = t >> 6, j = t & 63;
                int s = s_sel[b];
                if (s >= 0) {
                    unsigned char vh  = s_vh[b][j];
                    unsigned char pk  = s_pk[b][j];
                    float         cw  = s_cw[b][j];
                    unsigned char vh1 = (j < 63) ? s_vh[b][j + 1] : vh;
                    unsigned char pk1 = (j < 63) ? s_pk[b][j + 1] : pk;
                    float         cw1 = (j < 63) ? s_cw[b][j + 1] : cw;
                    nvh[t2] = (j < s) ? vh : ((j == s) ? pk : vh1);
                    bool sh = (j >= s);
                    npk[t2] = sh ? pk1 : pk;
                    ncw[t2] = sh ? cw1 : cw;
                } else { nvh[t2] = 0; npk[t2] = 0; ncw[t2] = 0.f; }
            }
            __syncthreads();
            #pragma unroll
            for (int t2 = 0; t2 < 16; t2++) {
                int t = tid + 256 * t2;
                int b = t >> 6, j = t & 63;
                if (s_sel[b] >= 0) {
                    s_vh[b][j] = nvh[t2];
                    s_pk[b][j] = npk[t2];
                    s_cw[b][j] = ncw[t2];
                }
            }
        }
        __syncthreads();

        // ---- (b3) rows setup ----
        if (tid == 0) {
            int acc = 0;
            for (int b = 0; b < BB; b++) { s_roff[b] = acc; acc += s_rcnt[b]; }
            s_nrows = acc;
        }
        __syncthreads();
        if (tid < BB) {
            int b = tid; int2 fr = s_fresh[b]; int o = s_roff[b];
            if (fr.x >= 0) {                  // (old, NEW)
                int p = fr.x;
                s_rows[o] = make_int4(b * NSLOT + s_vh[b][p], b * NSLOT + s_vh[b][p + 1],
                                      b * NSLOT + s_pk[b][p], b * 2 + 0);
                s_rb[o] = (unsigned char)b; s_rln[o] = 0; s_rrn[o] = 1; o++;
            }
            if (fr.y >= 0) {                  // (NEW, old)
                int p = fr.y;
                s_rows[o] = make_int4(b * NSLOT + s_vh[b][p], b * NSLOT + s_vh[b][p + 1],
                                      b * NSLOT + s_pk[b][p], b * 2 + 1);
                s_rb[o] = (unsigned char)b; s_rln[o] = 1; s_rrn[o] = 0; o++;
            }
        }
        __syncthreads();

        const int nrows = s_nrows;

        // ---- prefetch epilogue operands (hidden under GEMM) ----
        float pvl[2][5], pvr[2][5], clv[2], crv[2];
        #pragma unroll
        for (int r = 0; r < 2; r++) {
            int row = v * 2 + r;
            if (row < nrows) {
                int4 ri = s_rows[row];
                clv[r] = __ldcg(&g_C[ri.x * 512 + hg]);
                crv[r] = __ldcg(&g_C[ri.y * 512 + hg]);
                if (!s_rln[row]) {
                    #pragma unroll
                    for (int g = 0; g < 5; g++)
                        pvl[r][g] = __ldcg(&g_V[(ri.x * 2 + 0) * 2560 + g * 512 + hg]);
                }
                if (!s_rrn[row]) {
                    #pragma unroll
                    for (int g = 0; g < 5; g++)
                        pvr[r][g] = __ldcg(&g_V[(ri.y * 2 + 1) * 2560 + g * 512 + hg]);
                }
            } else { clv[r] = 0.f; crv[r] = 0.f; }
        }

        // ---- (c) vV GEMM for merged nodes: M=64, K=512, 40 outs/block ----
        if (i < 62) {
            const int ni = s_nodeidx[v];
            float2 acc[10];
            #pragma unroll
            for (int a = 0; a < 10; a++) acc[a] = make_float2(0.f, 0.f);

            float4 pf[4];
            #pragma unroll
            for (int t = 0; t < 4; t++)
                pf[t] = (ni >= 0)
                      ? __ldcg((const float4*)&g_H[ni * 512 + (u + 4 * t) * 4])
                      : make_float4(0.f, 0.f, 0.f, 0.f);
            #pragma unroll
            for (int t = 0; t < 4; t++)
                ((float4*)(Asb0 + v * A_STRIDE))[u + 4 * t] = pf[t];
            __syncthreads();

            for (int c = 0; c < 8; c++) {
                if (c < 7) {
                    #pragma unroll
                    for (int t = 0; t < 4; t++)
                        pf[t] = (ni >= 0)
                              ? __ldcg((const float4*)&g_H[ni * 512 + (c + 1) * 64 + (u + 4 * t) * 4])
                              : make_float4(0.f, 0.f, 0.f, 0.f);
                }
                const float* A = (c & 1) ? Asb1 : Asb0;
                if (ni >= 0) {
                    #pragma unroll
                    for (int k4 = 0; k4 < 16; k4++) {
                        float4 av = ((const float4*)(A + v * A_STRIDE))[k4];
                        float2 alo = make_float2(av.x, av.y);
                        float2 ahi = make_float2(av.z, av.w);
                        #pragma unroll
                        for (int a = 0; a < 10; a++) {
                            int r2 = (a >= 5 ? 20 : 0) + (a % 5) * 4 + u;
                            float4 wv = ((const float4*)(Wres + r2 * W_STRIDE))[c * 16 + k4];
                            ffma2(acc[a], alo, make_float2(wv.x, wv.y));
                            ffma2(acc[a], ahi, make_float2(wv.z, wv.w));
                        }
                    }
                }
                if (c < 7) {
                    float* An = (c & 1) ? Asb0 : Asb1;
                    #pragma unroll
                    for (int t = 0; t < 4; t++)
                        ((float4*)(An + v * A_STRIDE))[u + 4 * t] = pf[t];
                }
                __syncthreads();
            }

            if (ni >= 0) {
                #pragma unroll
                for (int a = 0; a < 10; a++) {
                    int side = (a >= 5), g = a % 5;
                    float val = acc[a].x + acc[a].y;
                    sVnew[v * 40 + side * 20 + g * 4 + u] = val;
                    g_V[(ni * 2 + side) * 2560 + g * 512 + hg] = val;
                }
            }
            __syncthreads();
        }

        // ---- (d) epilogue ----
        if (nrows > 0) {
            float* cwdst = g_cwp[(i + 1) & 1];
            #pragma unroll
            for (int r = 0; r < 2; r++) {
                int row = v * 2 + r;
                float p = 0.f;
                if (row < nrows) {
                    int bb = s_rb[row];
                    float vg[5];
                    #pragma unroll
                    for (int g = 0; g < 5; g++) {
                        float L = s_rln[row] ? sVnew[bb * 40 + g * 4 + u]      : pvl[r][g];
                        float R = s_rrn[row] ? sVnew[bb * 40 + 20 + g * 4 + u] : pvr[r][g];
                        vg[g] = L + R;
                    }
                    float cn = clv[r] * sigm(vg[1] + bfl + 1.f) + crv[r] * sigm(vg[2] + bfr + 1.f)
                             + tanhf(vg[3] + bu) * sigm(vg[0] + bi);
                    float hn = sigm(vg[4] + bo) * tanhf(cn);
                    int nst = s_rows[row].z;
                    g_H[nst * 512 + hg] = hn;
                    g_C[nst * 512 + hg] = cn;
                    p = hn * qv;
                }
                p += __shfl_xor_sync(0xffffffffu, p, 1);
                p += __shfl_xor_sync(0xffffffffu, p, 2);
                if (row < nrows && u == 0) cwdst[s_rows[row].w * 128 + blk] = p;
            }
        }
        target += GRID; grid_barrier(target);
    }

    // ---- output ----
    if (blk < BB) {
        int base = (blk * NSLOT + s_vh[blk][0]) * 512;
        out[blk * 512 + tid]                  = __ldcg(&g_H[base + tid]);
        out[blk * 512 + 256 + tid]            = __ldcg(&g_H[base + 256 + tid]);
        out[BB * 512 + blk * 512 + tid]       = __ldcg(&g_C[base + tid]);
        out[BB * 512 + blk * 512 + 256 + tid] = __ldcg(&g_C[base + 256 + tid]);
    }
}

// ---------------------------------------------------------------------------
extern "C" void kernel_launch(void* const* d_in, const int* in_sizes, int n_in,
                              void* d_out, int out_size)
{
    const float* x      = (const float*)d_in[0];
    const int*   length = (const int*)  d_in[1];
    const float* w_word = (const float*)d_in[2];
    const float* b_word = (const float*)d_in[3];
    const float* w_comp = (const float*)d_in[4];
    const float* b_comp = (const float*)d_in[5];
    const float* q      = (const float*)d_in[6];
    float* out = (float*)d_out;

    static int smem_set = 0;
    if (!smem_set) {
        cudaFuncSetAttribute(tree_loop, cudaFuncAttributeMaxDynamicSharedMemorySize,
                             SMEM_BYTES);
        smem_set = 1;
    }

    noop_k<<<1, 32>>>();
    word_gemm<<<dim3(16, 64), 256>>>(x, w_word, b_word);
    init_state<<<1, 32>>>();
    vv_full<<<dim3(128, 32), 256>>>(w_comp);
    pair_epi<<<4032, 256>>>(b_comp, q);
    tree_loop<<<GRID, TPB, SMEM_BYTES>>>(length, q, w_comp, b_comp, out);
}